// round 16
// baseline (speedup 1.0000x reference)
#include <cuda_runtime.h>

// CapsNet dynamic routing, factorized. 1 batch/CTA, T=576, 2 CTAs/SM.
// R16 = R15 with T=576: P2 = 576 exact tasks (8 s each, jh/sh shfl-folded),
// P5 = exactly 10 rounds/warp, P6 = exactly 2 n/thread.

namespace {
constexpr int O_ = 10, U_ = 36, E_ = 16, F_ = 8;
constexpr int N_ = 1152;
constexpr int B_ = 256;
constexpr int T_ = 576;              // 18 warps, 2 CTAs/SM
constexpr int NP = 1157;             // c plane stride

// shared layout (floats)
constexpr int OFF_XS = 0;                    // swizzled x [N][F]       9216
constexpr int OFF_C  = OFF_XS + N_ * F_;     // c [O][NP]              11570
constexpr int OFF_P  = (OFF_C + O_ * NP + 3) & ~3;  // pb 720 float4 (16B-aligned)
constexpr int OFF_VV = OFF_P + 2880;         // [O][E]                   160
constexpr int SM_FLOATS = OFF_VV + 160;      // -> 95,312 B
} // namespace

using ull = unsigned long long;

__device__ __forceinline__ int xsw(int i) { return i ^ ((i >> 3) & 7); }

__device__ __forceinline__ ull pack2(float lo, float hi) {
    ull r; asm("mov.b64 %0, {%1, %2};" : "=l"(r) : "f"(lo), "f"(hi)); return r;
}
__device__ __forceinline__ void unpack2(ull v, float& lo, float& hi) {
    asm("mov.b64 {%0, %1}, %2;" : "=f"(lo), "=f"(hi) : "l"(v));
}
__device__ __forceinline__ ull fma2(ull a, ull b, ull c) {
    ull d; asm("fma.rn.f32x2 %0, %1, %2, %3;" : "=l"(d) : "l"(a), "l"(b), "l"(c)); return d;
}
__device__ __forceinline__ ull add2(ull a, ull b) {
    ull d; asm("add.rn.f32x2 %0, %1, %2;" : "=l"(d) : "l"(a), "l"(b)); return d;
}
__device__ __forceinline__ ull mul2(ull a, ull b) {
    ull d; asm("mul.rn.f32x2 %0, %1, %2;" : "=l"(d) : "l"(a), "l"(b)); return d;
}

__global__ __launch_bounds__(T_, 2)
void caps_route_kernel(const float* __restrict__ x,
                       const float* __restrict__ Wg,
                       float* __restrict__ out) {
    extern __shared__ float sm[];
    float* cc  = sm + OFF_C;
    float* pbf = sm + OFF_P;
    float* vv  = sm + OFF_VV;
    float4* xs4 = reinterpret_cast<float4*>(sm + OFF_XS);
    float4* pb4 = reinterpret_cast<float4*>(pbf);

    const int tid = threadIdx.x;
    const int b = blockIdx.x;
    const int warp = tid >> 5;
    const int lane = tid & 31;

    const ulonglong2* __restrict__ wpu = reinterpret_cast<const ulonglong2*>(Wg);

    // ---- load x tile (coalesced gmem read, swizzled smem store) ----
    {
        const float4* xg = reinterpret_cast<const float4*>(x) + (size_t)b * (N_ * F_ / 4);
        #pragma unroll
        for (int i = tid; i < N_ * F_ / 4; i += T_) xs4[xsw(i)] = xg[i];
    }
    __syncthreads();

    // P2 task decode (576 tasks): tid = u<<4 | oh<<3 | fg<<2 | sh<<1 | jh
    const int p2_jh = tid & 1;
    const int p2_sh = (tid >> 1) & 1;
    const int p2_fg = (tid >> 2) & 1;
    const int p2_oh = (tid >> 3) & 1;
    const int p2_u  = tid >> 4;
    const float* p2_cbase = cc + p2_oh * 5 * NP + p2_u * 32 + p2_sh * 16;
    const int p2_pbase = (p2_u * 32 + p2_sh * 16) * 2 + p2_fg;
    const int p2_s0 = p2_jh * 8;
    float4* p2_pr = pb4 + (tid >> 2) * 5;    // task' = (u,oh,fg); sh,jh folded away

    // P3 decode: warp = o (<10); lane = e*2 + fh (lane-linear W)
    const int p3_e  = lane >> 1;
    const int p3_fh = lane & 1;

    // P5 decode: half-warp per task; lanep = e8*2 + fh
    const int p5_th = lane >> 4;          // task half (0/1)
    const int p5_lp = lane & 15;
    const int p5_e8 = p5_lp >> 1;
    const int p5_fh = p5_lp & 1;
    const int p5_s1 = (lane >> 1) & 1;
    const int p5_s2 = (lane >> 2) & 1;
    const int p5_f  = p5_fh * 4 + p5_s1 * 2 + p5_s2;

    for (int it = 0; it < 4; ++it) {
        // ---- P2: y partials; ALL 576 threads; 8 s each; fold jh (xor1), sh (xor2) ----
        {
            ull acc[10];
            #pragma unroll
            for (int r = 0; r < 10; ++r) acc[r] = 0ull;   // (0.f, 0.f)
            if (it == 0) {
                ull sA = 0ull, sB = 0ull;
                #pragma unroll
                for (int j = 0; j < 8; ++j) {
                    const int s = (p2_u + p2_s0 + j) & 15;
                    const ulonglong2 xv =
                        *reinterpret_cast<const ulonglong2*>(&xs4[xsw(p2_pbase + 2 * s)]);
                    sA = add2(sA, xv.x);
                    sB = add2(sB, xv.y);
                }
                const ull tenth = pack2(0.1f, 0.1f);
                sA = mul2(sA, tenth);
                sB = mul2(sB, tenth);
                #pragma unroll
                for (int oi = 0; oi < 5; ++oi) { acc[2 * oi] = sA; acc[2 * oi + 1] = sB; }
            } else {
                #pragma unroll
                for (int j = 0; j < 8; ++j) {
                    const int s = (p2_u + p2_s0 + j) & 15;  // rotation: spread banks
                    const ulonglong2 xv =
                        *reinterpret_cast<const ulonglong2*>(&xs4[xsw(p2_pbase + 2 * s)]);
                    #pragma unroll
                    for (int oi = 0; oi < 5; ++oi) {
                        const float cv = p2_cbase[oi * NP + s];
                        const ull c2 = pack2(cv, cv);
                        acc[2 * oi]     = fma2(c2, xv.x, acc[2 * oi]);
                        acc[2 * oi + 1] = fma2(c2, xv.y, acc[2 * oi + 1]);
                    }
                }
            }
            // fold jh (lane bit 0), then sh (lane bit 1)
            #pragma unroll
            for (int r = 0; r < 10; ++r) {
                acc[r] = add2(acc[r], __shfl_xor_sync(0xffffffffu, acc[r], 1));
                acc[r] = add2(acc[r], __shfl_xor_sync(0xffffffffu, acc[r], 2));
            }
            if ((tid & 3) == 0) {
                ulonglong2* pr = reinterpret_cast<ulonglong2*>(p2_pr);
                #pragma unroll
                for (int oi = 0; oi < 5; ++oi) {
                    ulonglong2 v;
                    v.x = acc[2 * oi];
                    v.y = acc[2 * oi + 1];
                    pr[oi] = v;
                }
            }
        }
        __syncthreads();

        // ---- P3 (+fused squash): warp=o, lane=(e,fh), lane-linear W, f32x2,
        //      unroll 12 + dual accumulators for LDG MLP / shorter fma chain ----
        if (warp < 10) {
            const int o = warp;
            const int oh = (o >= 5);
            const int k = o - 5 * oh;
            const int rbase = (oh * 2 + p3_fh) * 5 + k;
            const ulonglong2* wp = wpu + o * 36 * 32 + lane;
            ull accA = 0ull, accB = 0ull;
            #pragma unroll 12
            for (int u = 0; u < 36; u += 2) {
                const ulonglong2 w0 = wp[u * 32];
                const ulonglong2 w1 = wp[(u + 1) * 32];
                const ulonglong2 A0 =
                    *reinterpret_cast<const ulonglong2*>(&pb4[u * 20 + rbase]);
                const ulonglong2 A1 =
                    *reinterpret_cast<const ulonglong2*>(&pb4[(u + 1) * 20 + rbase]);
                accA = fma2(w0.x, A0.x, accA);
                accB = fma2(w0.y, A0.y, accB);
                accA = fma2(w1.x, A1.x, accA);
                accB = fma2(w1.y, A1.y, accB);
            }
            const ull accT = add2(accA, accB);
            float plo, phi;
            unpack2(accT, plo, phi);
            const float p0 = plo + phi;
            const float s0 = p0 + __shfl_xor_sync(0xffffffffu, p0, 1);
            float nsq0 = s0 * s0;
            #pragma unroll
            for (int m = 2; m <= 16; m <<= 1)
                nsq0 += __shfl_xor_sync(0xffffffffu, nsq0, m);
            if (p3_fh == 0) vv[o * 16 + p3_e] = s0 * (sqrtf(nsq0) / (1.f + nsq0));
        }
        __syncthreads();

        if (it == 3) break;

        // ---- P5: wv[o,u,f]; TWO tasks per warp round; exactly 10 rounds/warp ----
        #pragma unroll 2
        for (int pi = warp; pi < 180; pi += 18) {
            const int task = pi * 2 + p5_th;
            const ulonglong2 w0 = wpu[task * 32 + p5_lp];        // e = e8
            const ulonglong2 w1 = wpu[task * 32 + 16 + p5_lp];   // e = e8+8
            const int o = task / 36;
            const float v0 = vv[o * 16 + p5_e8];
            const float v1 = vv[o * 16 + 8 + p5_e8];
            const ull v0p = pack2(v0, v0);
            const ull v1p = pack2(v1, v1);
            ull acc01 = fma2(w0.x, v0p, mul2(w1.x, v1p));   // f = fh*4 + {0,1}
            ull acc23 = fma2(w0.y, v0p, mul2(w1.y, v1p));   // f = fh*4 + {2,3}
            const ull keep1 = p5_s1 ? acc23 : acc01;
            const ull send1 = p5_s1 ? acc01 : acc23;
            const ull r1 = add2(keep1, __shfl_xor_sync(0xffffffffu, send1, 2));
            float rlo, rhi;
            unpack2(r1, rlo, rhi);
            const float keep2 = p5_s2 ? rhi : rlo;
            const float send2 = p5_s2 ? rlo : rhi;
            float r2 = keep2 + __shfl_xor_sync(0xffffffffu, send2, 4);
            r2 += __shfl_xor_sync(0xffffffffu, r2, 8);
            if (p5_lp < 8) pbf[task * 8 + p5_f] = r2;
        }
        __syncthreads();

        // ---- P6: c <- normalize_o( c * exp(x . wv) ); exactly 2 n/thread ----
        #pragma unroll
        for (int kk = 0; kk < 2; ++kk) {
            const int n = tid + T_ * kk;
            const int u = n >> 5;
            const int q = xsw(n * 2);
            const ulonglong2 x0 = *reinterpret_cast<const ulonglong2*>(&xs4[q]);
            const ulonglong2 x1 = *reinterpret_cast<const ulonglong2*>(&xs4[q ^ 1]);
            const float4* wvb = pb4 + u * 2;
            float* cp = cc + n;
            float t[O_];
            float ss = 0.f;
            if (it > 0) {
                #pragma unroll
                for (int o = 0; o < O_; ++o) t[o] = cp[o * NP];   // issue loads early
            }
            #pragma unroll
            for (int o = 0; o < O_; ++o) {
                const ulonglong2 wA = *reinterpret_cast<const ulonglong2*>(&wvb[o * 72]);
                const ulonglong2 wB = *reinterpret_cast<const ulonglong2*>(&wvb[o * 72 + 1]);
                ull d0 = fma2(x0.y, wA.y, mul2(x0.x, wA.x));
                ull d1 = fma2(x1.y, wB.y, mul2(x1.x, wB.x));
                const ull dsum = add2(d0, d1);
                float dlo, dhi;
                unpack2(dsum, dlo, dhi);
                const float d = dlo + dhi;
                const float tv = (it == 0 ? 0.1f : t[o]) * __expf(d);
                t[o] = tv;
                ss += tv;
            }
            const float inv = 1.0f / ss;
            #pragma unroll
            for (int o = 0; o < O_; ++o) cp[o * NP] = t[o] * inv;
        }
        __syncthreads();
    }

    // ---- write out[b][o][e] ----
    if (tid < O_ * E_) {
        out[(size_t)b * (O_ * E_) + tid] = vv[tid];
    }
}

extern "C" void kernel_launch(void* const* d_in, const int* in_sizes, int n_in,
                              void* d_out, int out_size) {
    (void)in_sizes; (void)n_in; (void)out_size;
    const float* x = (const float*)d_in[0];
    const float* W = (const float*)d_in[1];
    float* out = (float*)d_out;

    const size_t smem = (size_t)SM_FLOATS * sizeof(float);  // 95,312 B
    cudaFuncSetAttribute(caps_route_kernel,
                         cudaFuncAttributeMaxDynamicSharedMemorySize, (int)smem);
    caps_route_kernel<<<B_, T_, smem>>>(x, W, out);
}

// round 17
// speedup vs baseline: 1.0175x; 1.0175x over previous
#include <cuda_runtime.h>

// CapsNet dynamic routing, factorized. 1 batch/CTA, T=512, 2 CTAs/SM.
// R17 = R15 + pre-barrier W prefetch for P3 (first 6 u) and P5 (round 0),
// overlapping the cold L2 latency with barrier waits.

namespace {
constexpr int O_ = 10, U_ = 36, E_ = 16, F_ = 8;
constexpr int N_ = 1152;
constexpr int B_ = 256;
constexpr int T_ = 512;              // 16 warps, 2 CTAs/SM
constexpr int NP = 1157;             // c plane stride

// shared layout (floats)
constexpr int OFF_XS = 0;                    // swizzled x [N][F]       9216
constexpr int OFF_C  = OFF_XS + N_ * F_;     // c [O][NP]              11570
constexpr int OFF_P  = (OFF_C + O_ * NP + 3) & ~3;  // pb 720 float4 (16B-aligned)
constexpr int OFF_VV = OFF_P + 2880;         // [O][E]                   160
constexpr int SM_FLOATS = OFF_VV + 160;      // -> 95,312 B
} // namespace

using ull = unsigned long long;

__device__ __forceinline__ int xsw(int i) { return i ^ ((i >> 3) & 7); }

__device__ __forceinline__ ull pack2(float lo, float hi) {
    ull r; asm("mov.b64 %0, {%1, %2};" : "=l"(r) : "f"(lo), "f"(hi)); return r;
}
__device__ __forceinline__ void unpack2(ull v, float& lo, float& hi) {
    asm("mov.b64 {%0, %1}, %2;" : "=f"(lo), "=f"(hi) : "l"(v));
}
__device__ __forceinline__ ull fma2(ull a, ull b, ull c) {
    ull d; asm("fma.rn.f32x2 %0, %1, %2, %3;" : "=l"(d) : "l"(a), "l"(b), "l"(c)); return d;
}
__device__ __forceinline__ ull add2(ull a, ull b) {
    ull d; asm("add.rn.f32x2 %0, %1, %2;" : "=l"(d) : "l"(a), "l"(b)); return d;
}
__device__ __forceinline__ ull mul2(ull a, ull b) {
    ull d; asm("mul.rn.f32x2 %0, %1, %2;" : "=l"(d) : "l"(a), "l"(b)); return d;
}

__global__ __launch_bounds__(T_, 2)
void caps_route_kernel(const float* __restrict__ x,
                       const float* __restrict__ Wg,
                       float* __restrict__ out) {
    extern __shared__ float sm[];
    float* cc  = sm + OFF_C;
    float* pbf = sm + OFF_P;
    float* vv  = sm + OFF_VV;
    float4* xs4 = reinterpret_cast<float4*>(sm + OFF_XS);
    float4* pb4 = reinterpret_cast<float4*>(pbf);

    const int tid = threadIdx.x;
    const int b = blockIdx.x;
    const int warp = tid >> 5;
    const int lane = tid & 31;

    const ulonglong2* __restrict__ wpu = reinterpret_cast<const ulonglong2*>(Wg);

    // ---- load x tile (coalesced gmem read, swizzled smem store) ----
    {
        const float4* xg = reinterpret_cast<const float4*>(x) + (size_t)b * (N_ * F_ / 4);
        #pragma unroll
        for (int i = tid; i < N_ * F_ / 4; i += T_) xs4[xsw(i)] = xg[i];
    }

    // P2 task decode (288 tasks): tid = u<<3 | oh<<2 | fg<<1 | sh  (sh = lane bit 0)
    const int p2_sh = tid & 1;
    const int p2_fg = (tid >> 1) & 1;
    const int p2_oh = (tid >> 2) & 1;
    const int p2_u  = tid >> 3;
    const float* p2_cbase = cc + p2_oh * 5 * NP + p2_u * 32 + p2_sh * 16;
    const int p2_pbase = (p2_u * 32 + p2_sh * 16) * 2 + p2_fg;
    float4* p2_pr = pb4 + (tid >> 1) * 5;    // task' = (u,oh,fg), sh reduced away

    // P3 decode: warp = o (<10); lane = e*2 + fh (lane-linear W)
    const int p3_e  = lane >> 1;
    const int p3_fh = lane & 1;
    const ulonglong2* wp3 = wpu + warp * 36 * 32 + lane;   // valid use only if warp<10

    // P5 decode: half-warp per task; lanep = e8*2 + fh
    const int p5_th = lane >> 4;          // task half (0/1)
    const int p5_lp = lane & 15;
    const int p5_e8 = p5_lp >> 1;
    const int p5_fh = p5_lp & 1;
    const int p5_s1 = (lane >> 1) & 1;
    const int p5_s2 = (lane >> 2) & 1;
    const int p5_f  = p5_fh * 4 + p5_s1 * 2 + p5_s2;
    const int p5_task0 = warp * 2 + p5_th;

    // P5 round body
    auto p5body = [&](int task, ulonglong2 w0, ulonglong2 w1) {
        const int o = task / 36;
        const float v0 = vv[o * 16 + p5_e8];
        const float v1 = vv[o * 16 + 8 + p5_e8];
        const ull v0p = pack2(v0, v0);
        const ull v1p = pack2(v1, v1);
        ull acc01 = fma2(w0.x, v0p, mul2(w1.x, v1p));   // f = fh*4 + {0,1}
        ull acc23 = fma2(w0.y, v0p, mul2(w1.y, v1p));   // f = fh*4 + {2,3}
        const ull keep1 = p5_s1 ? acc23 : acc01;
        const ull send1 = p5_s1 ? acc01 : acc23;
        const ull r1 = add2(keep1, __shfl_xor_sync(0xffffffffu, send1, 2));
        float rlo, rhi;
        unpack2(r1, rlo, rhi);
        const float keep2 = p5_s2 ? rhi : rlo;
        const float send2 = p5_s2 ? rlo : rhi;
        float r2 = keep2 + __shfl_xor_sync(0xffffffffu, send2, 4);
        r2 += __shfl_xor_sync(0xffffffffu, r2, 8);
        if (p5_lp < 8) pbf[task * 8 + p5_f] = r2;
    };

    __syncthreads();

    for (int it = 0; it < 4; ++it) {
        // ---- P2: y partials for (u,fg,oh); f32x2 FMA; sh halves merged via shfl ----
        if (tid < 288) {
            ull acc[10];
            #pragma unroll
            for (int r = 0; r < 10; ++r) acc[r] = 0ull;   // (0.f, 0.f)
            if (it == 0) {
                ull sA = 0ull, sB = 0ull;
                #pragma unroll
                for (int j = 0; j < 16; ++j) {
                    const ulonglong2 xv =
                        *reinterpret_cast<const ulonglong2*>(&xs4[xsw(p2_pbase + 2 * j)]);
                    sA = add2(sA, xv.x);
                    sB = add2(sB, xv.y);
                }
                const ull tenth = pack2(0.1f, 0.1f);
                sA = mul2(sA, tenth);
                sB = mul2(sB, tenth);
                #pragma unroll
                for (int oi = 0; oi < 5; ++oi) { acc[2 * oi] = sA; acc[2 * oi + 1] = sB; }
            } else {
                #pragma unroll
                for (int j = 0; j < 16; ++j) {
                    const int s = (p2_u + j) & 15;          // rotation: spread banks
                    const ulonglong2 xv =
                        *reinterpret_cast<const ulonglong2*>(&xs4[xsw(p2_pbase + 2 * s)]);
                    #pragma unroll
                    for (int oi = 0; oi < 5; ++oi) {
                        const float cv = p2_cbase[oi * NP + s];
                        const ull c2 = pack2(cv, cv);
                        acc[2 * oi]     = fma2(c2, xv.x, acc[2 * oi]);
                        acc[2 * oi + 1] = fma2(c2, xv.y, acc[2 * oi + 1]);
                    }
                }
            }
            #pragma unroll
            for (int r = 0; r < 10; ++r)
                acc[r] = add2(acc[r], __shfl_xor_sync(0xffffffffu, acc[r], 1));
            if (p2_sh == 0) {
                ulonglong2* pr = reinterpret_cast<ulonglong2*>(p2_pr);
                #pragma unroll
                for (int oi = 0; oi < 5; ++oi) {
                    ulonglong2 v;
                    v.x = acc[2 * oi];
                    v.y = acc[2 * oi + 1];
                    pr[oi] = v;
                }
            }
        }

        // ---- P3 W prefetch (u=0..5), pre-barrier: latency hides in BAR wait ----
        ulonglong2 wpre0, wpre1, wpre2, wpre3, wpre4, wpre5;
        if (warp < 10) {
            wpre0 = wp3[0];
            wpre1 = wp3[32];
            wpre2 = wp3[64];
            wpre3 = wp3[96];
            wpre4 = wp3[128];
            wpre5 = wp3[160];
        }
        __syncthreads();

        // ---- P3 (+fused squash): warp=o, lane=(e,fh), lane-linear W, f32x2 ----
        if (warp < 10) {
            const int o = warp;
            const int oh = (o >= 5);
            const int k = o - 5 * oh;
            const int rbase = (oh * 2 + p3_fh) * 5 + k;
            ull accA = 0ull, accB = 0ull;
            // prefetched u = 0..5
            {
                const ulonglong2 A0 = *reinterpret_cast<const ulonglong2*>(&pb4[rbase]);
                const ulonglong2 A1 = *reinterpret_cast<const ulonglong2*>(&pb4[20 + rbase]);
                const ulonglong2 A2 = *reinterpret_cast<const ulonglong2*>(&pb4[40 + rbase]);
                const ulonglong2 A3 = *reinterpret_cast<const ulonglong2*>(&pb4[60 + rbase]);
                const ulonglong2 A4 = *reinterpret_cast<const ulonglong2*>(&pb4[80 + rbase]);
                const ulonglong2 A5 = *reinterpret_cast<const ulonglong2*>(&pb4[100 + rbase]);
                accA = fma2(wpre0.x, A0.x, accA);
                accB = fma2(wpre0.y, A0.y, accB);
                accA = fma2(wpre1.x, A1.x, accA);
                accB = fma2(wpre1.y, A1.y, accB);
                accA = fma2(wpre2.x, A2.x, accA);
                accB = fma2(wpre2.y, A2.y, accB);
                accA = fma2(wpre3.x, A3.x, accA);
                accB = fma2(wpre3.y, A3.y, accB);
                accA = fma2(wpre4.x, A4.x, accA);
                accB = fma2(wpre4.y, A4.y, accB);
                accA = fma2(wpre5.x, A5.x, accA);
                accB = fma2(wpre5.y, A5.y, accB);
            }
            #pragma unroll 10
            for (int u = 6; u < 36; u += 2) {
                const ulonglong2 w0 = wp3[u * 32];
                const ulonglong2 w1 = wp3[(u + 1) * 32];
                const ulonglong2 A0 =
                    *reinterpret_cast<const ulonglong2*>(&pb4[u * 20 + rbase]);
                const ulonglong2 A1 =
                    *reinterpret_cast<const ulonglong2*>(&pb4[(u + 1) * 20 + rbase]);
                accA = fma2(w0.x, A0.x, accA);
                accB = fma2(w0.y, A0.y, accB);
                accA = fma2(w1.x, A1.x, accA);
                accB = fma2(w1.y, A1.y, accB);
            }
            const ull accT = add2(accA, accB);
            float plo, phi;
            unpack2(accT, plo, phi);
            const float p0 = plo + phi;
            const float s0 = p0 + __shfl_xor_sync(0xffffffffu, p0, 1);
            float nsq0 = s0 * s0;
            #pragma unroll
            for (int m = 2; m <= 16; m <<= 1)
                nsq0 += __shfl_xor_sync(0xffffffffu, nsq0, m);
            if (p3_fh == 0) vv[o * 16 + p3_e] = s0 * (sqrtf(nsq0) / (1.f + nsq0));
        }

        // ---- P5 round-0 W prefetch, pre-barrier ----
        const ulonglong2 p5w0 = wpu[p5_task0 * 32 + p5_lp];
        const ulonglong2 p5w1 = wpu[p5_task0 * 32 + 16 + p5_lp];
        __syncthreads();

        if (it == 3) break;

        // ---- P5: wv[o,u,f]; two tasks per warp round; round 0 prefetched ----
        p5body(p5_task0, p5w0, p5w1);
        #pragma unroll 2
        for (int pi = warp + 16; pi < 180; pi += 16) {
            const int task = pi * 2 + p5_th;
            const ulonglong2 w0 = wpu[task * 32 + p5_lp];
            const ulonglong2 w1 = wpu[task * 32 + 16 + p5_lp];
            p5body(task, w0, w1);
        }
        __syncthreads();

        // ---- P6: c <- normalize_o( c * exp(x . wv) ); dual f32x2 chains ----
        #pragma unroll
        for (int kk = 0; kk < 3; ++kk) {
            const int n = tid + T_ * kk;
            if (n < N_) {
                const int u = n >> 5;
                const int q = xsw(n * 2);
                const ulonglong2 x0 = *reinterpret_cast<const ulonglong2*>(&xs4[q]);
                const ulonglong2 x1 = *reinterpret_cast<const ulonglong2*>(&xs4[q ^ 1]);
                const float4* wvb = pb4 + u * 2;
                float* cp = cc + n;
                float t[O_];
                float ss = 0.f;
                if (it > 0) {
                    #pragma unroll
                    for (int o = 0; o < O_; ++o) t[o] = cp[o * NP];   // issue loads early
                }
                #pragma unroll
                for (int o = 0; o < O_; ++o) {
                    const ulonglong2 wA = *reinterpret_cast<const ulonglong2*>(&wvb[o * 72]);
                    const ulonglong2 wB = *reinterpret_cast<const ulonglong2*>(&wvb[o * 72 + 1]);
                    ull d0 = fma2(x0.y, wA.y, mul2(x0.x, wA.x));
                    ull d1 = fma2(x1.y, wB.y, mul2(x1.x, wB.x));
                    const ull dsum = add2(d0, d1);
                    float dlo, dhi;
                    unpack2(dsum, dlo, dhi);
                    const float d = dlo + dhi;
                    const float tv = (it == 0 ? 0.1f : t[o]) * __expf(d);
                    t[o] = tv;
                    ss += tv;
                }
                const float inv = 1.0f / ss;
                #pragma unroll
                for (int o = 0; o < O_; ++o) cp[o * NP] = t[o] * inv;
            }
        }
        __syncthreads();
    }

    // ---- write out[b][o][e] ----
    if (tid < O_ * E_) {
        out[(size_t)b * (O_ * E_) + tid] = vv[tid];
    }
}

extern "C" void kernel_launch(void* const* d_in, const int* in_sizes, int n_in,
                              void* d_out, int out_size) {
    (void)in_sizes; (void)n_in; (void)out_size;
    const float* x = (const float*)d_in[0];
    const float* W = (const float*)d_in[1];
    float* out = (float*)d_out;

    const size_t smem = (size_t)SM_FLOATS * sizeof(float);  // 95,312 B
    cudaFuncSetAttribute(caps_route_kernel,
                         cudaFuncAttributeMaxDynamicSharedMemorySize, (int)smem);
    caps_route_kernel<<<B_, T_, smem>>>(x, W, out);
}